// round 16
// baseline (speedup 1.0000x reference)
#include <cuda_runtime.h>
#include <cstdint>

// CRPS loss. R6 load structure (2px/thread, 34 scalar front-batched LDG.32,
// best measured effective BW) with NT=512 (256 CTAs: half the tail events)
// and a fixed-point u64 atomic accumulator: integer atomics are
// order-independent -> deterministic, and the finalize reads one u64 from
// L2 instead of a 2KB partials array from DRAM.
// term2 via sort identity sum_{i<j}|xi-xj| = sum_k (2k-15) x_(k).

#define NS     16
#define P      262144
#define NT     512
#define PX     2
#define NB     (P / (NT * PX))   // 256 blocks
#define STRIDE (NB * NT)         // 131072
#define FXSCALE 16777216.0       // 2^24

__device__ unsigned long long g_iacc = 0ull;
__device__ unsigned int       g_count = 0;

__device__ __forceinline__ void cas(float& a, float& b) {
    float lo = fminf(a, b);
    float hi = fmaxf(a, b);
    a = lo; b = hi;
}

__device__ __forceinline__ float crps_px(float v[NS], float t) {
    // term1: sum_i |s_i - y|
    float a1 = 0.f;
#pragma unroll
    for (int i = 0; i < NS; i++) a1 += fabsf(v[i] - t);

    // Batcher odd-even mergesort, n=16 (63 CAS)
#pragma unroll
    for (int pp = 1; pp < NS; pp <<= 1) {
#pragma unroll
        for (int k = pp; k >= 1; k >>= 1) {
#pragma unroll
            for (int j = k % pp; j + k < NS; j += 2 * k) {
#pragma unroll
                for (int i = 0; i < k && i + j + k < NS; i++) {
                    if ((i + j) / (2 * pp) == (i + j + k) / (2 * pp))
                        cas(v[i + j], v[i + j + k]);
                }
            }
        }
    }

    // term2 raw: sum_k (2k-15) x_(k)
    float a2 = 0.f;
#pragma unroll
    for (int k = 0; k < NS; k++)
        a2 = fmaf((float)(2 * k - 15), v[k], a2);

    return a1 * (1.0f / 16.0f) - a2 * (1.0f / 256.0f);
}

__global__ void __launch_bounds__(NT, 2)
k_crps(const float* __restrict__ s, const float* __restrict__ y,
       float* __restrict__ out) {
    const int p0 = blockIdx.x * NT + threadIdx.x;
    const int p1 = p0 + STRIDE;

    // Front-batched loads for BOTH pixels (32 sample LDG + 2 target LDG).
    float v0[NS], v1[NS];
#pragma unroll
    for (int i = 0; i < NS; i++) v0[i] = __ldg(&s[i * P + p0]);
#pragma unroll
    for (int i = 0; i < NS; i++) v1[i] = __ldg(&s[i * P + p1]);
    const float t0 = __ldg(&y[p0]);
    const float t1 = __ldg(&y[p1]);

    float val = crps_px(v0, t0);
    val      += crps_px(v1, t1);

    // Block reduction (warp shuffle + smem)
#pragma unroll
    for (int o = 16; o > 0; o >>= 1)
        val += __shfl_xor_sync(0xFFFFFFFFu, val, o);

    __shared__ float sm[NT / 32];
    const int lane = threadIdx.x & 31;
    const int wid  = threadIdx.x >> 5;
    if (lane == 0) sm[wid] = val;
    __syncthreads();

    if (wid == 0) {
        float w = (lane < NT / 32) ? sm[lane] : 0.f;
#pragma unroll
        for (int o = 8; o > 0; o >>= 1)
            w += __shfl_xor_sync(0xFFFFFFFFu, w, o);
        if (lane == 0) {
            // fixed-point, order-independent accumulation (deterministic)
            long long q = __double2ll_rn((double)w * FXSCALE);
            atomicAdd(&g_iacc, (unsigned long long)q);
            __threadfence();
            // completion count; last block finalizes
            if (atomicAdd(&g_count, 1u) == NB - 1) {
                __threadfence();
                long long tot = (long long)g_iacc;
                *out = (float)((double)tot * (1.0 / (FXSCALE * (double)P)));
                g_iacc  = 0ull;     // reset for next graph replay
                g_count = 0;
            }
        }
    }
}

extern "C" void kernel_launch(void* const* d_in, const int* in_sizes, int n_in,
                              void* d_out, int out_size) {
    const float* samples = (const float*)d_in[0];
    const float* target  = (const float*)d_in[1];
    k_crps<<<NB, NT>>>(samples, target, (float*)d_out);
}

// round 17
// speedup vs baseline: 1.0269x; 1.0269x over previous
#include <cuda_runtime.h>
#include <cstdint>

// CRPS loss — best measured hot kernel (ncu 9.216us, DRAM 1.94 TB/s).
// R6 load structure (2px/thread, 34 scalar front-batched LDG.32) at NT=512
// (256 CTAs -> half the tail events) with a fixed-point u64 atomic
// accumulator: integer atomics are order-independent -> deterministic
// across graph replays; finalize reads one u64 from L2 instead of a 2KB
// partials array from DRAM.
// term2 via sort identity sum_{i<j}|xi-xj| = sum_k (2k-15) x_(k).

#define NS     16
#define P      262144
#define NT     512
#define PX     2
#define NB     (P / (NT * PX))   // 256 blocks
#define STRIDE (NB * NT)         // 131072
#define FXSCALE 16777216.0       // 2^24

__device__ unsigned long long g_iacc = 0ull;
__device__ unsigned int       g_count = 0;

__device__ __forceinline__ void cas(float& a, float& b) {
    float lo = fminf(a, b);
    float hi = fmaxf(a, b);
    a = lo; b = hi;
}

__device__ __forceinline__ float crps_px(float v[NS], float t) {
    // term1: sum_i |s_i - y|
    float a1 = 0.f;
#pragma unroll
    for (int i = 0; i < NS; i++) a1 += fabsf(v[i] - t);

    // Batcher odd-even mergesort, n=16 (63 CAS)
#pragma unroll
    for (int pp = 1; pp < NS; pp <<= 1) {
#pragma unroll
        for (int k = pp; k >= 1; k >>= 1) {
#pragma unroll
            for (int j = k % pp; j + k < NS; j += 2 * k) {
#pragma unroll
                for (int i = 0; i < k && i + j + k < NS; i++) {
                    if ((i + j) / (2 * pp) == (i + j + k) / (2 * pp))
                        cas(v[i + j], v[i + j + k]);
                }
            }
        }
    }

    // term2 raw: sum_k (2k-15) x_(k)
    float a2 = 0.f;
#pragma unroll
    for (int k = 0; k < NS; k++)
        a2 = fmaf((float)(2 * k - 15), v[k], a2);

    return a1 * (1.0f / 16.0f) - a2 * (1.0f / 256.0f);
}

__global__ void __launch_bounds__(NT, 2)
k_crps(const float* __restrict__ s, const float* __restrict__ y,
       float* __restrict__ out) {
    const int p0 = blockIdx.x * NT + threadIdx.x;
    const int p1 = p0 + STRIDE;

    // Front-batched loads for BOTH pixels (32 sample LDG + 2 target LDG).
    float v0[NS], v1[NS];
#pragma unroll
    for (int i = 0; i < NS; i++) v0[i] = __ldg(&s[i * P + p0]);
#pragma unroll
    for (int i = 0; i < NS; i++) v1[i] = __ldg(&s[i * P + p1]);
    const float t0 = __ldg(&y[p0]);
    const float t1 = __ldg(&y[p1]);

    float val = crps_px(v0, t0);
    val      += crps_px(v1, t1);

    // Block reduction (warp shuffle + smem)
#pragma unroll
    for (int o = 16; o > 0; o >>= 1)
        val += __shfl_xor_sync(0xFFFFFFFFu, val, o);

    __shared__ float sm[NT / 32];
    const int lane = threadIdx.x & 31;
    const int wid  = threadIdx.x >> 5;
    if (lane == 0) sm[wid] = val;
    __syncthreads();

    if (wid == 0) {
        float w = (lane < NT / 32) ? sm[lane] : 0.f;
#pragma unroll
        for (int o = 8; o > 0; o >>= 1)
            w += __shfl_xor_sync(0xFFFFFFFFu, w, o);
        if (lane == 0) {
            // fixed-point, order-independent accumulation (deterministic)
            long long q = __double2ll_rn((double)w * FXSCALE);
            atomicAdd(&g_iacc, (unsigned long long)q);
            __threadfence();
            // completion count; last block finalizes
            if (atomicAdd(&g_count, 1u) == NB - 1) {
                __threadfence();
                long long tot = (long long)g_iacc;
                *out = (float)((double)tot * (1.0 / (FXSCALE * (double)P)));
                g_iacc  = 0ull;     // reset for next graph replay
                g_count = 0;
            }
        }
    }
}

extern "C" void kernel_launch(void* const* d_in, const int* in_sizes, int n_in,
                              void* d_out, int out_size) {
    const float* samples = (const float*)d_in[0];
    const float* target  = (const float*)d_in[1];
    k_crps<<<NB, NT>>>(samples, target, (float*)d_out);
}